// round 2
// baseline (speedup 1.0000x reference)
#include <cuda_runtime.h>
#include <cstdint>
#include <math.h>

// Problem dims
#define B_   64
#define T_   512
#define I_   256
#define H_   1024
#define F_   11
#define BT   (B_ * T_)      // 32768
#define G4   (4 * H_)       // 4096

// Output layout (concat of reference return tuple, row-major each)
#define OUT_STATE_OFF  0
#define OUT_REWARD_OFF (BT * F_)                 // 360448
#define OUT_HT_OFF     (OUT_REWARD_OFF + BT)     // 393216
#define OUT_CT_OFF     (OUT_HT_OFF + B_ * H_)    // 458752

// ---------------------------------------------------------------------------
// Scratch (static device globals — no allocation allowed)
// ---------------------------------------------------------------------------
__device__ float g_Z[BT * G4];        // 512 MB: x @ W_ih^T + (b_ih + b_hh)
__device__ float g_r[BT * H_];        // 128 MB: LSTM hidden states per step
__device__ float g_sh[BT * H_];       // 128 MB: shared layer output
__device__ float g_proj[BT * 16];     // 2 MB: [logit_s, logit_r, proj_state(11), proj_r, pad, pad]
__device__ float g_h[2][B_ * H_];     // double-buffered h
__device__ float g_c[B_ * H_];        // cell state
__device__ unsigned g_bar_count;
__device__ volatile unsigned g_bar_gen;

// ---------------------------------------------------------------------------
// Software grid barrier (all blocks resident: grid <= 148 SMs)
// ---------------------------------------------------------------------------
__device__ __forceinline__ void grid_barrier() {
    __threadfence();
    __syncthreads();
    if (threadIdx.x == 0) {
        unsigned gen = g_bar_gen;
        if (atomicAdd(&g_bar_count, 1u) == gridDim.x - 1) {
            g_bar_count = 0;
            __threadfence();
            g_bar_gen = gen + 1;
        } else {
            while (g_bar_gen == gen) { }
        }
    }
    __syncthreads();
    __threadfence();
}

__global__ void init_bar_kernel() {
    g_bar_count = 0;
    g_bar_gen = 0;
}

// ---------------------------------------------------------------------------
// SGEMM: C[M,N] = A[M,K] * W[N,K]^T + bias1[n] + bias2[n]
// BM=BN=128, BK=16, 256 threads, 8x8 microtile. M,N divisible by 128, K by 16.
// ---------------------------------------------------------------------------
__global__ __launch_bounds__(256) void sgemm_tn(
    const float* __restrict__ A, const float* __restrict__ W,
    const float* __restrict__ bias1, const float* __restrict__ bias2,
    float* __restrict__ C, int M, int N, int K)
{
    __shared__ float As[16][132];
    __shared__ float Bs[16][132];
    const int tid = threadIdx.x;
    const int m0 = blockIdx.y * 128;
    const int n0 = blockIdx.x * 128;
    const int ty = tid >> 4, tx = tid & 15;     // compute: 8 rows (m), 8 cols (n)
    const int lr = tid >> 2, lc = tid & 3;      // load: 64 rows/pass, 4 float4 per row

    float acc[8][8];
#pragma unroll
    for (int i = 0; i < 8; i++)
#pragma unroll
        for (int j = 0; j < 8; j++) acc[i][j] = 0.f;

    for (int k0 = 0; k0 < K; k0 += 16) {
#pragma unroll
        for (int p = 0; p < 2; p++) {
            const int r = lr + p * 64;
            const float4 va = *reinterpret_cast<const float4*>(
                A + (size_t)(m0 + r) * K + k0 + lc * 4);
            As[lc * 4 + 0][r] = va.x; As[lc * 4 + 1][r] = va.y;
            As[lc * 4 + 2][r] = va.z; As[lc * 4 + 3][r] = va.w;
            const float4 vb = *reinterpret_cast<const float4*>(
                W + (size_t)(n0 + r) * K + k0 + lc * 4);
            Bs[lc * 4 + 0][r] = vb.x; Bs[lc * 4 + 1][r] = vb.y;
            Bs[lc * 4 + 2][r] = vb.z; Bs[lc * 4 + 3][r] = vb.w;
        }
        __syncthreads();
#pragma unroll
        for (int k = 0; k < 16; k++) {
            float a[8], b[8];
            *reinterpret_cast<float4*>(a)     = *reinterpret_cast<const float4*>(&As[k][ty * 8]);
            *reinterpret_cast<float4*>(a + 4) = *reinterpret_cast<const float4*>(&As[k][ty * 8 + 4]);
            *reinterpret_cast<float4*>(b)     = *reinterpret_cast<const float4*>(&Bs[k][tx * 8]);
            *reinterpret_cast<float4*>(b + 4) = *reinterpret_cast<const float4*>(&Bs[k][tx * 8 + 4]);
#pragma unroll
            for (int i = 0; i < 8; i++)
#pragma unroll
                for (int j = 0; j < 8; j++)
                    acc[i][j] += a[i] * b[j];
        }
        __syncthreads();
    }

#pragma unroll
    for (int i = 0; i < 8; i++) {
        const int row = m0 + ty * 8 + i;
#pragma unroll
        for (int j = 0; j < 8; j++) {
            const int col = n0 + tx * 8 + j;
            float v = acc[i][j];
            if (bias1) v += bias1[col];
            if (bias2) v += bias2[col];
            C[(size_t)row * N + col] = v;
        }
    }
}

// ---------------------------------------------------------------------------
// Persistent LSTM recurrence. 128 blocks x 256 threads, all co-resident.
// Block b owns hidden dims j in [b*8, b*8+8): computes the 32 gate rows
// (4 gates x 8 j) for all 64 batches each step, applies gates locally,
// writes h into the other buffer, then one grid barrier per step.
// ---------------------------------------------------------------------------
#define RBLK 128

__device__ __forceinline__ float sigf(float x) { return 1.f / (1.f + __expf(-x)); }

__global__ __launch_bounds__(256) void lstm_kernel(
    const float* __restrict__ Whh,
    const float* __restrict__ h0, const float* __restrict__ c0)
{
    const int tid = threadIdx.x, bid = blockIdx.x;

    // init h, c
    for (int i = bid * 256 + tid; i < B_ * H_; i += RBLK * 256) {
        g_h[0][i] = h0[i];
        g_c[i] = c0[i];
    }
    grid_barrier();

    __shared__ float As[16][68];   // h tile, transposed [k][b]
    __shared__ float Bs[16][36];   // W tile, transposed [k][n]
    __shared__ float zs[64][33];   // z tile [b][n], n = gate*8 + jj

    const int j0 = bid * 8;
    const int ty = tid >> 4, tx = tid & 15;   // compute: 4 batches x 2 n
    const int lk = tid & 15, lr = tid >> 4;   // load coords

    for (int t = 0; t < T_; t++) {
        const float* __restrict__ hcur = g_h[t & 1];
        float acc[4][2] = {{0.f,0.f},{0.f,0.f},{0.f,0.f},{0.f,0.f}};

        for (int k0 = 0; k0 < H_; k0 += 16) {
#pragma unroll
            for (int p = 0; p < 4; p++)
                As[lk][lr + p * 16] = hcur[(lr + p * 16) * H_ + k0 + lk];
#pragma unroll
            for (int p = 0; p < 2; p++) {
                const int nn = lr + p * 16;
                const int wrow = j0 + (nn & 7) + (nn >> 3) * H_;
                Bs[lk][nn] = Whh[(size_t)wrow * H_ + k0 + lk];
            }
            __syncthreads();
#pragma unroll
            for (int k = 0; k < 16; k++) {
                const float4 a = *reinterpret_cast<const float4*>(&As[k][ty * 4]);
                const float b0 = Bs[k][tx * 2], b1 = Bs[k][tx * 2 + 1];
                acc[0][0] += a.x * b0; acc[0][1] += a.x * b1;
                acc[1][0] += a.y * b0; acc[1][1] += a.y * b1;
                acc[2][0] += a.z * b0; acc[2][1] += a.z * b1;
                acc[3][0] += a.w * b0; acc[3][1] += a.w * b1;
            }
            __syncthreads();
        }

        // z = acc + Z (Z already includes both biases)
#pragma unroll
        for (int i = 0; i < 4; i++) {
            const int b = ty * 4 + i;
#pragma unroll
            for (int j = 0; j < 2; j++) {
                const int n = tx * 2 + j;
                const int col = (n >> 3) * H_ + j0 + (n & 7);
                zs[b][n] = acc[i][j] + g_Z[(size_t)(b * T_ + t) * G4 + col];
            }
        }
        __syncthreads();

        // gates: each thread handles 2 of the 512 (b, jj) entries
        float* __restrict__ hnxt = g_h[(t + 1) & 1];
#pragma unroll
        for (int r = 0; r < 2; r++) {
            const int e = tid + r * 256;
            const int b = e >> 3, jj = e & 7;
            const float zi = zs[b][jj];
            const float zf = zs[b][8 + jj];
            const float zg = zs[b][16 + jj];
            const float zo = zs[b][24 + jj];
            const int idx = b * H_ + j0 + jj;
            const float cc = sigf(zf) * g_c[idx] + sigf(zi) * tanhf(zg);
            const float hh = sigf(zo) * tanhf(cc);
            g_c[idx] = cc;
            hnxt[idx] = hh;
            g_r[(size_t)(b * T_ + t) * H_ + j0 + jj] = hh;
        }
        grid_barrier();
    }
}

// ---------------------------------------------------------------------------
// Heads: per row of g_sh, compute 14 dot products:
// [0]=logit_state, [1]=logit_reward, [2..12]=proj_state(11), [13]=proj_reward
// One warp per row.
// ---------------------------------------------------------------------------
__global__ __launch_bounds__(256) void heads_kernel(
    const float* __restrict__ w_att_s, const float* __restrict__ w_att_r,
    const float* __restrict__ W_state, const float* __restrict__ W_reward)
{
    const int warp = (blockIdx.x * blockDim.x + threadIdx.x) >> 5;
    const int lane = threadIdx.x & 31;
    if (warp >= BT) return;
    const float* rowp = g_sh + (size_t)warp * H_;

    float4 f[8];
#pragma unroll
    for (int i = 0; i < 8; i++)
        f[i] = *reinterpret_cast<const float4*>(rowp + lane * 32 + i * 4);

    float out[14];
#pragma unroll
    for (int fi = 0; fi < 14; fi++) {
        const float* wv = (fi == 0) ? w_att_s
                        : (fi == 1) ? w_att_r
                        : (fi < 13) ? (W_state + (fi - 2) * H_)
                        : W_reward;
        float s = 0.f;
#pragma unroll
        for (int i = 0; i < 8; i++) {
            const float4 w = *reinterpret_cast<const float4*>(wv + lane * 32 + i * 4);
            s += f[i].x * w.x + f[i].y * w.y + f[i].z * w.z + f[i].w * w.w;
        }
#pragma unroll
        for (int o = 16; o; o >>= 1) s += __shfl_xor_sync(0xffffffffu, s, o);
        out[fi] = s;
    }
    if (lane == 0) {
#pragma unroll
        for (int fi = 0; fi < 14; fi++)
            g_proj[(size_t)warp * 16 + fi] = out[fi];
    }
}

// ---------------------------------------------------------------------------
// Causal prefix-softmax scan over scalar logits, averaging the 12-dim
// projections. One block per batch: warp0 = state head, warp1 = reward head.
// ---------------------------------------------------------------------------
__global__ void scan_kernel(const float* __restrict__ b_state,
                            const float* __restrict__ b_reward,
                            float* __restrict__ out)
{
    const int b = blockIdx.x;
    const int w = threadIdx.x >> 5, lane = threadIdx.x & 31;
    const float* pbase = g_proj + (size_t)b * T_ * 16;

    if (w == 0) {
        float num = 0.f, den = 0.f, m = -INFINITY;
        const float bs = (lane < F_) ? b_state[lane] : 0.f;
        for (int t = 0; t < T_; t++) {
            const float* p = pbase + t * 16;
            const float l = p[0];
            const float v = (lane < F_) ? p[2 + lane] : 0.f;
            const float nm = fmaxf(m, l);
            const float sc = __expf(m - nm);
            const float e  = __expf(l - nm);
            den = den * sc + e;
            num = num * sc + e * v;
            m = nm;
            if (lane < F_)
                out[OUT_STATE_OFF + (size_t)(b * T_ + t) * F_ + lane] = num / den + bs;
        }
    } else if (w == 1) {
        float num = 0.f, den = 0.f, m = -INFINITY;
        const float br = b_reward[0];
        for (int t = 0; t < T_; t++) {
            const float* p = pbase + t * 16;
            const float l = p[1];
            const float v = p[13];
            const float nm = fmaxf(m, l);
            const float sc = __expf(m - nm);
            const float e  = __expf(l - nm);
            den = den * sc + e;
            num = num * sc + e * v;
            m = nm;
            if (lane == 0)
                out[OUT_REWARD_OFF + b * T_ + t] = num / den + br;
        }
    }
}

// ---------------------------------------------------------------------------
// Final hT / cT copy (h ended in buffer 0 after 512 steps)
// ---------------------------------------------------------------------------
__global__ void finalize_kernel(float* __restrict__ out)
{
    const int i = blockIdx.x * blockDim.x + threadIdx.x;
    if (i < B_ * H_) {
        out[OUT_HT_OFF + i] = g_h[0][i];
        out[OUT_CT_OFF + i] = g_c[i];
    }
}

// ---------------------------------------------------------------------------
// Launch
// ---------------------------------------------------------------------------
extern "C" void kernel_launch(void* const* d_in, const int* in_sizes, int n_in,
                              void* d_out, int out_size)
{
    const float* x        = (const float*)d_in[0];
    // d_in[1] = x_lengths (all == T, unused)
    const float* h0       = (const float*)d_in[2];
    const float* c0       = (const float*)d_in[3];
    const float* W_ih     = (const float*)d_in[4];
    const float* W_hh     = (const float*)d_in[5];
    const float* b_ih     = (const float*)d_in[6];
    const float* b_hh     = (const float*)d_in[7];
    const float* W_sh     = (const float*)d_in[8];
    const float* b_sh     = (const float*)d_in[9];
    const float* w_att_s  = (const float*)d_in[10];
    // d_in[11] = b_att_s (cancels in softmax)
    const float* w_att_r  = (const float*)d_in[12];
    // d_in[13] = b_att_r (cancels in softmax)
    const float* W_state  = (const float*)d_in[14];
    const float* b_state  = (const float*)d_in[15];
    const float* W_reward = (const float*)d_in[16];
    const float* b_reward = (const float*)d_in[17];
    float* out = (float*)d_out;

    float *Z, *r, *sh;
    cudaGetSymbolAddress((void**)&Z,  g_Z);
    cudaGetSymbolAddress((void**)&r,  g_r);
    cudaGetSymbolAddress((void**)&sh, g_sh);

    // Z = x @ W_ih^T + (b_ih + b_hh)   [32768, 4096]
    sgemm_tn<<<dim3(G4 / 128, BT / 128), 256>>>(x, W_ih, b_ih, b_hh, Z, BT, G4, I_);

    // LSTM recurrence (persistent, 512 steps)
    init_bar_kernel<<<1, 1>>>();
    lstm_kernel<<<RBLK, 256>>>(W_hh, h0, c0);

    // shared = r_out @ W_sh^T + b_sh   [32768, 1024]
    sgemm_tn<<<dim3(H_ / 128, BT / 128), 256>>>(r, W_sh, b_sh, nullptr, sh, BT, H_, H_);

    // 14-way projection (logits + head projections)
    heads_kernel<<<BT / 8, 256>>>(w_att_s, w_att_r, W_state, W_reward);

    // causal prefix-softmax scans -> state_out, reward_out
    scan_kernel<<<B_, 64>>>(b_state, b_reward, out);

    // hT, cT
    finalize_kernel<<<(B_ * H_ + 255) / 256, 256>>>(out);
}